// round 11
// baseline (speedup 1.0000x reference)
#include <cuda_runtime.h>

#define T_LEN 1024
#define B_LEN 256
#define EMB   512
#define ATT   128
#define NF    32
#define NPROD 12
#define NCONS 4

// ---------- packed f32x2 helpers ----------
__device__ __forceinline__ unsigned long long PK(float a, float b) {
    unsigned long long r;
    asm("mov.b64 %0,{%1,%2};" : "=l"(r) : "f"(a), "f"(b));
    return r;
}
__device__ __forceinline__ float2 UPK(unsigned long long u) {
    float2 v;
    asm("mov.b64 {%0,%1},%2;" : "=f"(v.x), "=f"(v.y) : "l"(u));
    return v;
}
__device__ __forceinline__ unsigned long long FMA2(unsigned long long a,
                                                   unsigned long long b,
                                                   unsigned long long c) {
    asm("fma.rn.f32x2 %0, %1, %2, %0;" : "+l"(c) : "l"(a), "l"(b));
    return c;
}
__device__ __forceinline__ unsigned long long ADD2(unsigned long long a,
                                                   unsigned long long b) {
    unsigned long long r;
    asm("add.rn.f32x2 %0, %1, %2;" : "=l"(r) : "l"(a), "l"(b));
    return r;
}

__device__ __forceinline__ float tanh_f(float x) {
    float e = __expf(2.0f * x);
    return 1.0f - __fdividef(2.0f, e + 1.0f);
}

__device__ __forceinline__ unsigned smem_u32(const void* p) {
    unsigned a;
    asm("{ .reg .u64 t; cvta.to.shared.u64 t, %1; cvt.u32.u64 %0, t; }"
        : "=r"(a) : "l"(p));
    return a;
}
__device__ __forceinline__ void mbar_init(unsigned addr, unsigned cnt) {
    asm volatile("mbarrier.init.shared.b64 [%0], %1;" ::"r"(addr), "r"(cnt)
                 : "memory");
}
__device__ __forceinline__ void mbar_arrive(unsigned addr) {
    asm volatile("mbarrier.arrive.release.cta.shared::cta.b64 _, [%0];" ::"r"(addr)
                 : "memory");
}
__device__ __forceinline__ void mbar_wait(unsigned addr, unsigned parity) {
    asm volatile(
        "{\n\t.reg .pred P;\n"
        "WL%=:\n\t"
        "mbarrier.try_wait.parity.acquire.cta.shared::cta.b64 P, [%0], %1, 0x989680;\n\t"
        "@!P bra WL%=;\n\t}"
        ::"r"(addr), "r"(parity) : "memory");
}
__device__ __forceinline__ void pf_l2(const void* p) {
    asm volatile("prefetch.global.L2 [%0];" ::"l"(p));
}

#define BAR_SYNC(id, cnt) \
    asm volatile("bar.sync %0, %1;" ::"r"(id), "r"(cnt) : "memory")

// smem layout (bytes):
//   aw2 16896 | wc2 16128 | wl4 16384 | v2 512 | cvd 12*4608=55296 |
//   e_sm 4096 | red 128 | scr 8192 | mbar 64  => ~117.7 KB
#define CVD_ROW 36  /* floats per f-row: 8 dup-float4 (32) + 4 pad */
#define SMEM_BYTES (16896 + 16128 + 16384 + 512 + NPROD * 32 * CVD_ROW * 4 + 4096 + 128 + NCONS * 128 * 16 + 64)

__global__ __launch_bounds__(512, 1) void attn_fused(
    const float* __restrict__ query, const float* __restrict__ memory,
    const float* __restrict__ pmem, const float* __restrict__ awcat,
    const unsigned char* __restrict__ mask, const float* __restrict__ wq,
    const float* __restrict__ wconv, const float* __restrict__ wll,
    const float* __restrict__ v, float* __restrict__ outC,
    float* __restrict__ outW) {
    extern __shared__ unsigned long long sm[];
    unsigned long long* aw2 = sm;                          // 2112 ull
    unsigned long long* wc2 = aw2 + 2112;                  // 2016 ull
    float4* wl4 = (float4*)(wc2 + 2016);                   // 1024 f4
    float2* v2 = (float2*)(wl4 + 1024);                    // 64 f2
    float* cvd = (float*)(v2 + 64);                        // 12*32*36 floats
    float* e_sm = cvd + NPROD * 32 * CVD_ROW;              // 1024
    float* red = e_sm + T_LEN;                             // 32
    float4* scr = (float4*)(red + 32);                     // NCONS*128
    unsigned long long* mbar = (unsigned long long*)(scr + NCONS * 128);
    float* pq_s = cvd;                                     // transient
    float* qs = e_sm;                                      // transient

    const int b = blockIdx.x, tid = threadIdx.x;
    const int w = tid >> 5, lane = tid & 31;
    const unsigned mbar0 = smem_u32(mbar);

    if (tid == 0) {
#pragma unroll
        for (int c = 0; c < 8; c++) mbar_init(mbar0 + c * 8, 8);
    }

    // ---- stage shared operands (all 512 threads) ----
    const float* awb = awcat + (size_t)b * 2 * T_LEN;
    for (int i = tid; i < 2112; i += 512) {
        int c = (i < 1056) ? 0 : 1;
        int p = i - c * 1056;
        float x0 = (p >= 15 && p < 1039) ? awb[c * T_LEN + p - 15] : 0.f;
        float x1 = (p >= 14 && p < 1038) ? awb[c * T_LEN + p - 14] : 0.f;
        aw2[i] = PK(x0, x1);
    }
    for (int i = tid; i < 1984; i += 512) {
        int f = i / 62, m = i - f * 62;
        float x = wconv[i];
        wc2[f * 63 + m] = PK(x, x);
    }
    // wl4[f][l] = {wll[2l][f], wll[2l+1][f], wll[64+2l][f], wll[65+2l][f]}
    for (int i = tid; i < 1024; i += 512) {
        int f = i >> 5, l = i & 31;
        wl4[f * 32 + l] =
            make_float4(wll[(2 * l) * NF + f], wll[(2 * l + 1) * NF + f],
                        wll[(64 + 2 * l) * NF + f], wll[(65 + 2 * l) * NF + f]);
    }
    if (tid < 64) v2[tid] = make_float2(v[2 * tid], v[2 * tid + 1]);
    for (int i = tid; i < 1024; i += 512) qs[i] = query[(size_t)b * 1024 + i];
    __syncthreads();  // staging + mbarrier init visible

    if (w < NPROD) {
        // ================== ENERGY PRODUCER WARPS (12) ==================
        if (w < 8) {
            const unsigned long long* q2 = (const unsigned long long*)qs;
#pragma unroll 4
            for (int ai = 0; ai < 16; ai++) {
                int a = w * 16 + ai;
                const unsigned long long* wq2 =
                    (const unsigned long long*)(wq + (size_t)a * 1024);
                unsigned long long acc = 0ull;
#pragma unroll
                for (int m = 0; m < 16; m++)
                    acc = FMA2(q2[m * 32 + lane], wq2[m * 32 + lane], acc);
                float2 p = UPK(acc);
                float s = p.x + p.y;
#pragma unroll
                for (int off = 16; off; off >>= 1)
                    s += __shfl_xor_sync(0xffffffffu, s, off);
                if (lane == 0) pq_s[a] = s;
            }
        }
        BAR_SYNC(2, 32 * NPROD);
        const unsigned long long pqau = PK(pq_s[2 * lane], pq_s[2 * lane + 1]);
        const unsigned long long pqbu =
            PK(pq_s[64 + 2 * lane], pq_s[64 + 2 * lane + 1]);
        const float2 va = v2[lane], vb = v2[lane + 32];
        BAR_SYNC(2, 32 * NPROD);  // pq_s consumed; cvd writable

        const unsigned long long* pm2 =
            (const unsigned long long*)(pmem + (size_t)b * T_LEN * ATT);
        float* cvb = cvd + w * 32 * CVD_ROW;
        float S_loc = 0.f;

        for (int s = w; s < 64; s += NPROD) {
            const int t0 = s * 16;
            // prefetch this slice's pm rows into L2 (8KB contiguous)
            {
                const char* pfb = (const char*)(pm2 + (size_t)t0 * 64);
                pf_l2(pfb + lane * 128);
                pf_l2(pfb + lane * 128 + 4096);
            }
            // conv: 16 t's (8 pairs), filter = lane
            unsigned long long cp[8];
#pragma unroll
            for (int j = 0; j < 8; j++) cp[j] = 0ull;
            {
                const unsigned long long* wcb = wc2 + lane * 63;
#pragma unroll
                for (int ch = 0; ch < 2; ch++) {
                    const unsigned long long* aw = aw2 + ch * 1056 + t0;
                    unsigned long long rg[15];
#pragma unroll
                    for (int i = 0; i < 15; i++) rg[i] = aw[i];
#pragma unroll
                    for (int k = 0; k < 31; k++) {
                        unsigned long long wv = wcb[ch * 31 + k];
#pragma unroll
                        for (int j = 0; j < 8; j++)
                            cp[j] = FMA2(rg[2 * j], wv, cp[j]);
                        if (k < 30) {
#pragma unroll
                            for (int i = 0; i < 14; i++) rg[i] = rg[i + 1];
                            rg[14] = aw[k + 15];
                        }
                    }
                }
            }
            // store duplicated: row f=lane, float4 {x,x,y,y} per t-pair j
            {
                float4* row = (float4*)(cvb + lane * CVD_ROW);
#pragma unroll
                for (int j = 0; j < 8; j++) {
                    float2 c2 = UPK(cp[j]);
                    row[j] = make_float4(c2.x, c2.x, c2.y, c2.y);
                }
            }
            __syncwarp();

#pragma unroll
            for (int half = 0; half < 2; half++) {
                const int tbb = t0 + half * 8;
                unsigned long long sacc[8][2];
#pragma unroll
                for (int tt = 0; tt < 8; tt++) {
                    sacc[tt][0] =
                        ADD2(pqau, __ldcs(&pm2[(size_t)(tbb + tt) * 64 + lane]));
                    sacc[tt][1] = ADD2(
                        pqbu, __ldcs(&pm2[(size_t)(tbb + tt) * 64 + 32 + lane]));
                }
#pragma unroll 8
                for (int f = 0; f < NF; f++) {
                    float4 w4 = wl4[f * 32 + lane];
                    unsigned long long w0 = PK(w4.x, w4.y);
                    unsigned long long w1 = PK(w4.z, w4.w);
                    const unsigned long long* crow =
                        (const unsigned long long*)(cvb + f * CVD_ROW) + half * 8;
#pragma unroll
                    for (int j = 0; j < 4; j++) {
                        unsigned long long cX = crow[2 * j];      // {c(t2j),c(t2j)}
                        unsigned long long cY = crow[2 * j + 1];  // {c(t2j+1),...}
                        sacc[2 * j][0] = FMA2(cX, w0, sacc[2 * j][0]);
                        sacc[2 * j][1] = FMA2(cX, w1, sacc[2 * j][1]);
                        sacc[2 * j + 1][0] = FMA2(cY, w0, sacc[2 * j + 1][0]);
                        sacc[2 * j + 1][1] = FMA2(cY, w1, sacc[2 * j + 1][1]);
                    }
                }
                float e[8];
#pragma unroll
                for (int tt = 0; tt < 8; tt++) {
                    float2 x0 = UPK(sacc[tt][0]), x1 = UPK(sacc[tt][1]);
                    e[tt] = va.x * tanh_f(x0.x) + va.y * tanh_f(x0.y) +
                            vb.x * tanh_f(x1.x) + vb.y * tanh_f(x1.y);
                }
#pragma unroll
                for (int off = 16; off; off >>= 1) {
#pragma unroll
                    for (int tt = 0; tt < 8; tt++)
                        e[tt] += __shfl_xor_sync(0xffffffffu, e[tt], off);
                }
                if (lane == 0) {
                    const unsigned char* mb = mask + (size_t)b * T_LEN + tbb;
#pragma unroll
                    for (int tt = 0; tt < 8; tt++) {
                        // |e| <= ||v||_1 ~ 15 -> exp fp32-safe without max-sub
                        float ex = mb[tt] ? 0.f : __expf(e[tt]);
                        e_sm[tbb + tt] = ex;
                        S_loc += ex;
                    }
                }
            }
            // e_sm written by lane 0; arrive.release by lane 0 orders them
            if (lane == 0) mbar_arrive(mbar0 + (s >> 3) * 8);
        }
        if (lane == 0) red[w] = S_loc;
    } else {
        // ================== CONTEXT CONSUMER WARPS (4) ==================
        const int cw = w - NPROD;
        const float4* mem4 = (const float4*)(memory + (size_t)b * T_LEN * EMB);
        unsigned long long acc[4][2];
#pragma unroll
        for (int j = 0; j < 4; j++) acc[j][0] = acc[j][1] = 0ull;

        // prefetch chunk 0 region (64KB per warp) into L2
        {
            const char* pfb = (const char*)(mem4 + (size_t)(cw * 32) * 128);
#pragma unroll
            for (int i = 0; i < 16; i++) pf_l2(pfb + lane * 128 + i * 4096);
        }

        for (int c = 0; c < 8; c++) {
            mbar_wait(mbar0 + c * 8, 0);  // acquire chunk c energies
            // prefetch next chunk's region while streaming this one
            if (c < 7) {
                const char* pfb =
                    (const char*)(mem4 + (size_t)((c + 1) * 128 + cw * 32) * 128);
#pragma unroll
                for (int i = 0; i < 16; i++) pf_l2(pfb + lane * 128 + i * 4096);
            }
            const int tb = c * 128 + cw * 32;
            for (int tt = 0; tt < 32; tt += 4) {
                float4 mv[16];
#pragma unroll
                for (int u = 0; u < 4; u++)
#pragma unroll
                    for (int j = 0; j < 4; j++)
                        mv[u * 4 + j] = __ldcs(
                            &mem4[(size_t)(tb + tt + u) * 128 + lane + 32 * j]);
#pragma unroll
                for (int u = 0; u < 4; u++) {
                    float wt = e_sm[tb + tt + u];
                    unsigned long long W = PK(wt, wt);
#pragma unroll
                    for (int j = 0; j < 4; j++) {
                        float4 m = mv[u * 4 + j];
                        acc[j][0] = FMA2(W, PK(m.x, m.y), acc[j][0]);
                        acc[j][1] = FMA2(W, PK(m.z, m.w), acc[j][1]);
                    }
                }
            }
        }
#pragma unroll
        for (int j = 0; j < 4; j++) {
            float2 x0 = UPK(acc[j][0]), x1 = UPK(acc[j][1]);
            scr[cw * 128 + lane + 32 * j] = make_float4(x0.x, x0.y, x1.x, x1.y);
        }
    }

    __syncthreads();  // S partials + scr + e_sm final

    float S = 0.f;
#pragma unroll
    for (int i = 0; i < NPROD; i++) S += red[i];
    const float invS = 1.0f / S;

    float* oW = outW + (size_t)b * T_LEN;
    for (int i = tid; i < T_LEN; i += 512) oW[i] = e_sm[i] * invS;

    if (tid < 128) {
        float4 o = make_float4(0.f, 0.f, 0.f, 0.f);
#pragma unroll
        for (int q = 0; q < NCONS; q++) {
            float4 sq = scr[q * 128 + tid];
            o.x += sq.x; o.y += sq.y; o.z += sq.z; o.w += sq.w;
        }
        o.x *= invS; o.y *= invS; o.z *= invS; o.w *= invS;
        ((float4*)outC)[(size_t)b * 128 + tid] = o;
    }
}

extern "C" void kernel_launch(void* const* d_in, const int* in_sizes, int n_in,
                              void* d_out, int out_size) {
    const float* query = (const float*)d_in[0];
    const float* memory = (const float*)d_in[1];
    const float* pmem = (const float*)d_in[2];
    const float* awcat = (const float*)d_in[3];
    const unsigned char* mask = (const unsigned char*)d_in[4];
    const float* wq = (const float*)d_in[5];
    const float* wconv = (const float*)d_in[6];
    const float* wll = (const float*)d_in[7];
    const float* v = (const float*)d_in[8];

    float* outC = (float*)d_out;               // (B, 512)
    float* outW = outC + (size_t)B_LEN * EMB;  // (B, T)

    cudaFuncSetAttribute(attn_fused, cudaFuncAttributeMaxDynamicSharedMemorySize,
                         SMEM_BYTES);
    attn_fused<<<B_LEN, 512, SMEM_BYTES>>>(query, memory, pmem, awcat, mask, wq,
                                           wconv, wll, v, outC, outW);
}

// round 13
// speedup vs baseline: 1.1350x; 1.1350x over previous
#include <cuda_runtime.h>

#define T_LEN 1024
#define B_LEN 256
#define EMB   512
#define ATT   128
#define NF    32
#define NPROD 12
#define NCONS 4

// ---------- packed f32x2 helpers ----------
__device__ __forceinline__ unsigned long long PK(float a, float b) {
    unsigned long long r;
    asm("mov.b64 %0,{%1,%2};" : "=l"(r) : "f"(a), "f"(b));
    return r;
}
__device__ __forceinline__ float2 UPK(unsigned long long u) {
    float2 v;
    asm("mov.b64 {%0,%1},%2;" : "=f"(v.x), "=f"(v.y) : "l"(u));
    return v;
}
__device__ __forceinline__ unsigned long long FMA2(unsigned long long a,
                                                   unsigned long long b,
                                                   unsigned long long c) {
    asm("fma.rn.f32x2 %0, %1, %2, %0;" : "+l"(c) : "l"(a), "l"(b));
    return c;
}
__device__ __forceinline__ unsigned long long ADD2(unsigned long long a,
                                                   unsigned long long b) {
    unsigned long long r;
    asm("add.rn.f32x2 %0, %1, %2;" : "=l"(r) : "l"(a), "l"(b));
    return r;
}

__device__ __forceinline__ float tanh_f(float x) {
    float e = __expf(2.0f * x);
    return 1.0f - __fdividef(2.0f, e + 1.0f);
}

__device__ __forceinline__ unsigned smem_u32(const void* p) {
    unsigned a;
    asm("{ .reg .u64 t; cvta.to.shared.u64 t, %1; cvt.u32.u64 %0, t; }"
        : "=r"(a) : "l"(p));
    return a;
}
__device__ __forceinline__ void mbar_init(unsigned addr, unsigned cnt) {
    asm volatile("mbarrier.init.shared.b64 [%0], %1;" ::"r"(addr), "r"(cnt)
                 : "memory");
}
__device__ __forceinline__ void mbar_arrive(unsigned addr) {
    asm volatile("mbarrier.arrive.release.cta.shared::cta.b64 _, [%0];" ::"r"(addr)
                 : "memory");
}
__device__ __forceinline__ void mbar_wait(unsigned addr, unsigned parity) {
    asm volatile(
        "{\n\t.reg .pred P;\n"
        "WL%=:\n\t"
        "mbarrier.try_wait.parity.acquire.cta.shared::cta.b64 P, [%0], %1, 0x989680;\n\t"
        "@!P bra WL%=;\n\t}"
        ::"r"(addr), "r"(parity) : "memory");
}
__device__ __forceinline__ void pf_l2(const void* p) {
    asm volatile("prefetch.global.L2 [%0];" ::"l"(p));
}

#define BAR_SYNC(id, cnt) \
    asm volatile("bar.sync %0, %1;" ::"r"(id), "r"(cnt) : "memory")

// ---------- warp-specialized fused kernel (R10 base, 12/4 split) ----------
// 512 threads: warps 0-11 = energy producers, warps 12-15 = context consumers.
// Slice s (16 t's, s=0..63) -> producer warp s%12; chunk c = slices 8c..8c+7,
// its mbarrier counts 8 slice-arrivals (mapping-independent, deadlock-free).
// smem: aw2 2112ull | wc2 2016ull | wl2 2048ull | v2 64f2 | cv2 3072f2 |
//       e_sm 1024f | red 64f | scr 4*128 f4 | mbar 8 u64
#define SMEM_BYTES ((2112 + 2016 + 2048) * 8 + 64 * 8 + 3072 * 8 + 1024 * 4 + 64 * 4 + NCONS * 128 * 16 + 8 * 8)

__global__ __launch_bounds__(512, 1) void attn_fused(
    const float* __restrict__ query, const float* __restrict__ memory,
    const float* __restrict__ pmem, const float* __restrict__ awcat,
    const unsigned char* __restrict__ mask, const float* __restrict__ wq,
    const float* __restrict__ wconv, const float* __restrict__ wll,
    const float* __restrict__ v, float* __restrict__ outC,
    float* __restrict__ outW) {
    extern __shared__ unsigned long long sm[];
    unsigned long long* aw2 = sm;               // 2112
    unsigned long long* wc2 = aw2 + 2112;       // 2016
    unsigned long long* wl2 = wc2 + 2016;       // 2048
    float2* v2 = (float2*)(wl2 + 2048);         // 64
    float2* cv2 = v2 + 64;                      // 3072 (12 warps * 256)
    float* e_sm = (float*)(cv2 + 3072);         // 1024 (unnormalized exp)
    float* red = e_sm + T_LEN;                  // 64
    float4* scr = (float4*)(red + 64);          // NCONS*128
    unsigned long long* mbar = (unsigned long long*)(scr + NCONS * 128);  // 8
    float* pq_s = (float*)cv2;                  // transient (producer-only)
    float* qs = e_sm;                           // transient

    const int b = blockIdx.x, tid = threadIdx.x;
    const int w = tid >> 5, lane = tid & 31;
    const unsigned mbar0 = smem_u32(mbar);

    if (tid == 0) {
#pragma unroll
        for (int c = 0; c < 8; c++) mbar_init(mbar0 + c * 8, 8);
    }

    // ---- stage shared operands (all 512 threads) ----
    const float* awb = awcat + (size_t)b * 2 * T_LEN;
    for (int i = tid; i < 2112; i += 512) {
        int c = (i < 1056) ? 0 : 1;
        int p = i - c * 1056;
        float x0 = (p >= 15 && p < 1039) ? awb[c * T_LEN + p - 15] : 0.f;
        float x1 = (p >= 14 && p < 1038) ? awb[c * T_LEN + p - 14] : 0.f;
        aw2[i] = PK(x0, x1);
    }
    for (int i = tid; i < 1984; i += 512) {
        int f = i / 62, m = i - f * 62;
        float x = wconv[i];
        wc2[f * 63 + m] = PK(x, x);
    }
    for (int i = tid; i < 2048; i += 512) {
        int f = i >> 6, p = i & 63;
        wl2[i] = PK(wll[(2 * p) * NF + f], wll[(2 * p + 1) * NF + f]);
    }
    if (tid < 64) v2[tid] = make_float2(v[2 * tid], v[2 * tid + 1]);
    for (int i = tid; i < 1024; i += 512) qs[i] = query[(size_t)b * 1024 + i];
    __syncthreads();  // staging + mbarrier init visible

    if (w < NPROD) {
        // ================== ENERGY PRODUCER WARPS (12) ==================
        if (w < 8) {
            const unsigned long long* q2 = (const unsigned long long*)qs;
#pragma unroll 4
            for (int ai = 0; ai < 16; ai++) {
                int a = w * 16 + ai;
                const unsigned long long* wq2 =
                    (const unsigned long long*)(wq + (size_t)a * 1024);
                unsigned long long acc = 0ull;
#pragma unroll
                for (int m = 0; m < 16; m++)
                    acc = FMA2(q2[m * 32 + lane], wq2[m * 32 + lane], acc);
                float2 p = UPK(acc);
                float s = p.x + p.y;
#pragma unroll
                for (int off = 16; off; off >>= 1)
                    s += __shfl_xor_sync(0xffffffffu, s, off);
                if (lane == 0) pq_s[a] = s;
            }
        }
        BAR_SYNC(2, 32 * NPROD);
        const unsigned long long pqau = PK(pq_s[2 * lane], pq_s[2 * lane + 1]);
        const unsigned long long pqbu =
            PK(pq_s[64 + 2 * lane], pq_s[64 + 2 * lane + 1]);
        const float2 va = v2[lane], vb = v2[lane + 32];
        BAR_SYNC(2, 32 * NPROD);  // pq_s consumed; cv2 writable

        const unsigned long long* pm2 =
            (const unsigned long long*)(pmem + (size_t)b * T_LEN * ATT);
        float S_loc = 0.f;

        for (int s = w; s < 64; s += NPROD) {
            const int t0 = s * 16;
            // prefetch this slice's pm rows into L2 (8KB, hidden under conv)
            {
                const char* pfb = (const char*)(pm2 + (size_t)t0 * 64);
                pf_l2(pfb + lane * 128);
                pf_l2(pfb + lane * 128 + 4096);
            }
            // conv: 16 t's (8 pairs), filter = lane
            unsigned long long cp[8];
#pragma unroll
            for (int j = 0; j < 8; j++) cp[j] = 0ull;
            {
                const unsigned long long* wcb = wc2 + lane * 63;
#pragma unroll
                for (int ch = 0; ch < 2; ch++) {
                    const unsigned long long* aw = aw2 + ch * 1056 + t0;
                    unsigned long long rg[15];
#pragma unroll
                    for (int i = 0; i < 15; i++) rg[i] = aw[i];
#pragma unroll
                    for (int k = 0; k < 31; k++) {
                        unsigned long long wv = wcb[ch * 31 + k];
#pragma unroll
                        for (int j = 0; j < 8; j++)
                            cp[j] = FMA2(rg[2 * j], wv, cp[j]);
                        if (k < 30) {
#pragma unroll
                            for (int i = 0; i < 14; i++) rg[i] = rg[i + 1];
                            rg[14] = aw[k + 15];
                        }
                    }
                }
            }
#pragma unroll
            for (int j = 0; j < 8; j++) cv2[w * 256 + j * 32 + lane] = UPK(cp[j]);
            __syncwarp();

#pragma unroll
            for (int half = 0; half < 2; half++) {
                const int tbb = t0 + half * 8;
                unsigned long long sacc[8][2];
#pragma unroll
                for (int tt = 0; tt < 8; tt++) {
                    sacc[tt][0] =
                        ADD2(pqau, __ldcs(&pm2[(size_t)(tbb + tt) * 64 + lane]));
                    sacc[tt][1] = ADD2(
                        pqbu, __ldcs(&pm2[(size_t)(tbb + tt) * 64 + 32 + lane]));
                }
#pragma unroll 8
                for (int f = 0; f < NF; f++) {
                    unsigned long long w0 = wl2[f * 64 + lane];
                    unsigned long long w1 = wl2[f * 64 + 32 + lane];
#pragma unroll
                    for (int j = 0; j < 4; j++) {
                        float2 cc = cv2[w * 256 + (half * 4 + j) * 32 + f];
                        unsigned long long cX = PK(cc.x, cc.x);
                        unsigned long long cY = PK(cc.y, cc.y);
                        sacc[2 * j][0] = FMA2(cX, w0, sacc[2 * j][0]);
                        sacc[2 * j][1] = FMA2(cX, w1, sacc[2 * j][1]);
                        sacc[2 * j + 1][0] = FMA2(cY, w0, sacc[2 * j + 1][0]);
                        sacc[2 * j + 1][1] = FMA2(cY, w1, sacc[2 * j + 1][1]);
                    }
                }
                float e[8];
#pragma unroll
                for (int tt = 0; tt < 8; tt++) {
                    float2 x0 = UPK(sacc[tt][0]), x1 = UPK(sacc[tt][1]);
                    e[tt] = va.x * tanh_f(x0.x) + va.y * tanh_f(x0.y) +
                            vb.x * tanh_f(x1.x) + vb.y * tanh_f(x1.y);
                }
#pragma unroll
                for (int off = 16; off; off >>= 1) {
#pragma unroll
                    for (int tt = 0; tt < 8; tt++)
                        e[tt] += __shfl_xor_sync(0xffffffffu, e[tt], off);
                }
                if (lane == 0) {
                    const unsigned char* mb = mask + (size_t)b * T_LEN + tbb;
#pragma unroll
                    for (int tt = 0; tt < 8; tt++) {
                        // |e| <= ||v||_1 ~ 15 -> exp fp32-safe without max-sub
                        float ex = mb[tt] ? 0.f : __expf(e[tt]);
                        e_sm[tbb + tt] = ex;
                        S_loc += ex;
                    }
                }
            }
            __syncwarp();
            if (lane == 0) mbar_arrive(mbar0 + (s >> 3) * 8);  // publish slice
        }
        if (lane == 0) red[w] = S_loc;
    } else {
        // ================== CONTEXT CONSUMER WARPS (4) ==================
        const int cw = w - NPROD;
        const float4* mem4 = (const float4*)(memory + (size_t)b * T_LEN * EMB);
        unsigned long long acc[4][2];
#pragma unroll
        for (int j = 0; j < 4; j++) acc[j][0] = acc[j][1] = 0ull;

        for (int c = 0; c < 8; c++) {
            mbar_wait(mbar0 + c * 8, 0);  // acquire chunk c energies
            const int tb = c * 128 + cw * 32;
            for (int tt = 0; tt < 32; tt += 4) {
                float4 mv[16];
#pragma unroll
                for (int u = 0; u < 4; u++)
#pragma unroll
                    for (int j = 0; j < 4; j++)
                        mv[u * 4 + j] = __ldcs(
                            &mem4[(size_t)(tb + tt + u) * 128 + lane + 32 * j]);
#pragma unroll
                for (int u = 0; u < 4; u++) {
                    float wt = e_sm[tb + tt + u];
                    unsigned long long W = PK(wt, wt);
#pragma unroll
                    for (int j = 0; j < 4; j++) {
                        float4 m = mv[u * 4 + j];
                        acc[j][0] = FMA2(W, PK(m.x, m.y), acc[j][0]);
                        acc[j][1] = FMA2(W, PK(m.z, m.w), acc[j][1]);
                    }
                }
            }
        }
        // park per-warp partials (raw, unnormalized)
#pragma unroll
        for (int j = 0; j < 4; j++) {
            float2 x0 = UPK(acc[j][0]), x1 = UPK(acc[j][1]);
            scr[cw * 128 + lane + 32 * j] = make_float4(x0.x, x0.y, x1.x, x1.y);
        }
    }

    __syncthreads();  // S partials + scr + e_sm final

    float S = 0.f;
#pragma unroll
    for (int i = 0; i < NPROD; i++) S += red[i];
    const float invS = 1.0f / S;

    float* oW = outW + (size_t)b * T_LEN;
    for (int i = tid; i < T_LEN; i += 512) oW[i] = e_sm[i] * invS;

    if (tid < 128) {
        float4 o = make_float4(0.f, 0.f, 0.f, 0.f);
#pragma unroll
        for (int q = 0; q < NCONS; q++) {
            float4 sq = scr[q * 128 + tid];
            o.x += sq.x; o.y += sq.y; o.z += sq.z; o.w += sq.w;
        }
        o.x *= invS; o.y *= invS; o.z *= invS; o.w *= invS;
        ((float4*)outC)[(size_t)b * 128 + tid] = o;
    }
}

extern "C" void kernel_launch(void* const* d_in, const int* in_sizes, int n_in,
                              void* d_out, int out_size) {
    const float* query = (const float*)d_in[0];
    const float* memory = (const float*)d_in[1];
    const float* pmem = (const float*)d_in[2];
    const float* awcat = (const float*)d_in[3];
    const unsigned char* mask = (const unsigned char*)d_in[4];
    const float* wq = (const float*)d_in[5];
    const float* wconv = (const float*)d_in[6];
    const float* wll = (const float*)d_in[7];
    const float* v = (const float*)d_in[8];

    float* outC = (float*)d_out;               // (B, 512)
    float* outW = outC + (size_t)B_LEN * EMB;  // (B, T)

    cudaFuncSetAttribute(attn_fused, cudaFuncAttributeMaxDynamicSharedMemorySize,
                         SMEM_BYTES);
    attn_fused<<<B_LEN, 512, SMEM_BYTES>>>(query, memory, pmem, awcat, mask, wq,
                                           wconv, wll, v, outC, outW);
}

// round 15
// speedup vs baseline: 1.2979x; 1.1436x over previous
#include <cuda_runtime.h>

#define T_LEN 1024
#define B_LEN 256
#define EMB   512
#define ATT   128
#define NF    32

// ---------- packed f32x2 helpers ----------
__device__ __forceinline__ unsigned long long PK(float a, float b) {
    unsigned long long r;
    asm("mov.b64 %0,{%1,%2};" : "=l"(r) : "f"(a), "f"(b));
    return r;
}
__device__ __forceinline__ float2 UPK(unsigned long long u) {
    float2 v;
    asm("mov.b64 {%0,%1},%2;" : "=f"(v.x), "=f"(v.y) : "l"(u));
    return v;
}
__device__ __forceinline__ unsigned long long FMA2(unsigned long long a,
                                                   unsigned long long b,
                                                   unsigned long long c) {
    asm("fma.rn.f32x2 %0, %1, %2, %0;" : "+l"(c) : "l"(a), "l"(b));
    return c;
}
__device__ __forceinline__ unsigned long long ADD2(unsigned long long a,
                                                   unsigned long long b) {
    unsigned long long r;
    asm("add.rn.f32x2 %0, %1, %2;" : "=l"(r) : "l"(a), "l"(b));
    return r;
}

// tanh.approx.f32: max abs err ~6e-4 -> softmax weight rel err ~2-4e-4 (< 1e-3)
__device__ __forceinline__ float tanh_f(float x) {
    float r;
    asm("tanh.approx.f32 %0, %1;" : "=f"(r) : "f"(x));
    return r;
}

__device__ __forceinline__ unsigned smem_u32(const void* p) {
    unsigned a;
    asm("{ .reg .u64 t; cvta.to.shared.u64 t, %1; cvt.u32.u64 %0, t; }"
        : "=r"(a) : "l"(p));
    return a;
}
__device__ __forceinline__ void mbar_init(unsigned addr, unsigned cnt) {
    asm volatile("mbarrier.init.shared.b64 [%0], %1;" ::"r"(addr), "r"(cnt)
                 : "memory");
}
__device__ __forceinline__ void mbar_arrive(unsigned addr) {
    asm volatile("mbarrier.arrive.release.cta.shared::cta.b64 _, [%0];" ::"r"(addr)
                 : "memory");
}
__device__ __forceinline__ void mbar_wait(unsigned addr, unsigned parity) {
    asm volatile(
        "{\n\t.reg .pred P;\n"
        "WL%=:\n\t"
        "mbarrier.try_wait.parity.acquire.cta.shared::cta.b64 P, [%0], %1, 0x989680;\n\t"
        "@!P bra WL%=;\n\t}"
        ::"r"(addr), "r"(parity) : "memory");
}
__device__ __forceinline__ void pf_l2(const void* p) {
    asm volatile("prefetch.global.L2 [%0];" ::"l"(p));
}

#define BAR_SYNC(id, cnt) \
    asm volatile("bar.sync %0, %1;" ::"r"(id), "r"(cnt) : "memory")

// ---------- warp-specialized fused kernel (R10 base: 8 prod / 8 cons) ----------
// Per-chunk mbarrier (count=8, one arrive per producer warp) — phase-safe even
// if producers run arbitrarily ahead.
// smem: aw2 2112ull | wc2 2016ull | wl2 2048ull | v2 64f2 | cv2 2048f2 |
//       e_sm 1024f | red 64f | scr 8*128 f4 | mbar 8 u64
#define SMEM_BYTES ((2112 + 2016 + 2048) * 8 + 64 * 8 + 2048 * 8 + 1024 * 4 + 64 * 4 + 8 * 128 * 16 + 8 * 8)

__global__ __launch_bounds__(512, 1) void attn_fused(
    const float* __restrict__ query, const float* __restrict__ memory,
    const float* __restrict__ pmem, const float* __restrict__ awcat,
    const unsigned char* __restrict__ mask, const float* __restrict__ wq,
    const float* __restrict__ wconv, const float* __restrict__ wll,
    const float* __restrict__ v, float* __restrict__ outC,
    float* __restrict__ outW) {
    extern __shared__ unsigned long long sm[];
    unsigned long long* aw2 = sm;               // 2112
    unsigned long long* wc2 = aw2 + 2112;       // 2016
    unsigned long long* wl2 = wc2 + 2016;       // 2048
    float2* v2 = (float2*)(wl2 + 2048);         // 64
    float2* cv2 = v2 + 64;                      // 2048
    float* e_sm = (float*)(cv2 + 2048);         // 1024 (unnormalized exp)
    float* red = e_sm + T_LEN;                  // 64
    float4* scr = (float4*)(red + 64);          // 8*128
    unsigned long long* mbar = (unsigned long long*)(scr + 8 * 128);  // 8
    float* pq_s = (float*)cv2;                  // transient (producer-only)
    float* qs = e_sm;                           // transient

    const int b = blockIdx.x, tid = threadIdx.x;
    const int w = tid >> 5, lane = tid & 31;
    const unsigned mbar0 = smem_u32(mbar);

    if (tid == 0) {
#pragma unroll
        for (int c = 0; c < 8; c++) mbar_init(mbar0 + c * 8, 8);
    }

    // ---- stage shared operands (all 512 threads) ----
    const float* awb = awcat + (size_t)b * 2 * T_LEN;
    for (int i = tid; i < 2112; i += 512) {
        int c = (i < 1056) ? 0 : 1;
        int p = i - c * 1056;
        float x0 = (p >= 15 && p < 1039) ? awb[c * T_LEN + p - 15] : 0.f;
        float x1 = (p >= 14 && p < 1038) ? awb[c * T_LEN + p - 14] : 0.f;
        aw2[i] = PK(x0, x1);
    }
    for (int i = tid; i < 1984; i += 512) {
        int f = i / 62, m = i - f * 62;
        float x = wconv[i];
        wc2[f * 63 + m] = PK(x, x);
    }
    for (int i = tid; i < 2048; i += 512) {
        int f = i >> 6, p = i & 63;
        wl2[i] = PK(wll[(2 * p) * NF + f], wll[(2 * p + 1) * NF + f]);
    }
    if (tid < 64) v2[tid] = make_float2(v[2 * tid], v[2 * tid + 1]);
    for (int i = tid; i < 1024; i += 512) qs[i] = query[(size_t)b * 1024 + i];
    __syncthreads();  // staging + mbarrier init visible

    if (w < 8) {
        // ================== ENERGY PRODUCER WARPS ==================
        {
            const unsigned long long* q2 = (const unsigned long long*)qs;
#pragma unroll 4
            for (int ai = 0; ai < 16; ai++) {
                int a = w * 16 + ai;
                const unsigned long long* wq2 =
                    (const unsigned long long*)(wq + (size_t)a * 1024);
                unsigned long long acc = 0ull;
#pragma unroll
                for (int m = 0; m < 16; m++)
                    acc = FMA2(q2[m * 32 + lane], wq2[m * 32 + lane], acc);
                float2 p = UPK(acc);
                float s = p.x + p.y;
#pragma unroll
                for (int off = 16; off; off >>= 1)
                    s += __shfl_xor_sync(0xffffffffu, s, off);
                if (lane == 0) pq_s[a] = s;
            }
        }
        BAR_SYNC(2, 256);
        const unsigned long long pqau = PK(pq_s[2 * lane], pq_s[2 * lane + 1]);
        const unsigned long long pqbu =
            PK(pq_s[64 + 2 * lane], pq_s[64 + 2 * lane + 1]);
        const float2 va = v2[lane], vb = v2[lane + 32];
        BAR_SYNC(2, 256);  // pq_s consumed; cv2 writable

        const unsigned long long* pm2 =
            (const unsigned long long*)(pmem + (size_t)b * T_LEN * ATT);
        float S_loc = 0.f;

        for (int c = 0; c < 8; c++) {
            const int t0 = c * 128 + w * 16;
            // prefetch this round's pm rows into L2 (hidden under conv)
            {
                const char* pfb = (const char*)(pm2 + (size_t)t0 * 64);
                pf_l2(pfb + lane * 256);
                pf_l2(pfb + lane * 256 + 128);
            }
            // conv: 16 t's (8 pairs)
            unsigned long long cp[8];
#pragma unroll
            for (int j = 0; j < 8; j++) cp[j] = 0ull;
            {
                const unsigned long long* wcb = wc2 + lane * 63;
#pragma unroll
                for (int ch = 0; ch < 2; ch++) {
                    const unsigned long long* aw = aw2 + ch * 1056 + t0;
                    unsigned long long rg[15];
#pragma unroll
                    for (int i = 0; i < 15; i++) rg[i] = aw[i];
#pragma unroll
                    for (int k = 0; k < 31; k++) {
                        unsigned long long wv = wcb[ch * 31 + k];
#pragma unroll
                        for (int j = 0; j < 8; j++)
                            cp[j] = FMA2(rg[2 * j], wv, cp[j]);
                        if (k < 30) {
#pragma unroll
                            for (int i = 0; i < 14; i++) rg[i] = rg[i + 1];
                            rg[14] = aw[k + 15];
                        }
                    }
                }
            }
#pragma unroll
            for (int j = 0; j < 8; j++) cv2[w * 256 + j * 32 + lane] = UPK(cp[j]);
            __syncwarp();

#pragma unroll
            for (int half = 0; half < 2; half++) {
                const int tbb = t0 + half * 8;
                unsigned long long s[8][2];
#pragma unroll
                for (int tt = 0; tt < 8; tt++) {
                    s[tt][0] =
                        ADD2(pqau, __ldcs(&pm2[(size_t)(tbb + tt) * 64 + lane]));
                    s[tt][1] = ADD2(
                        pqbu, __ldcs(&pm2[(size_t)(tbb + tt) * 64 + 32 + lane]));
                }
#pragma unroll 8
                for (int f = 0; f < NF; f++) {
                    unsigned long long w0 = wl2[f * 64 + lane];
                    unsigned long long w1 = wl2[f * 64 + 32 + lane];
#pragma unroll
                    for (int j = 0; j < 4; j++) {
                        float2 cc = cv2[w * 256 + (half * 4 + j) * 32 + f];
                        unsigned long long cX = PK(cc.x, cc.x);
                        unsigned long long cY = PK(cc.y, cc.y);
                        s[2 * j][0] = FMA2(cX, w0, s[2 * j][0]);
                        s[2 * j][1] = FMA2(cX, w1, s[2 * j][1]);
                        s[2 * j + 1][0] = FMA2(cY, w0, s[2 * j + 1][0]);
                        s[2 * j + 1][1] = FMA2(cY, w1, s[2 * j + 1][1]);
                    }
                }
                float e[8];
#pragma unroll
                for (int tt = 0; tt < 8; tt++) {
                    float2 x0 = UPK(s[tt][0]), x1 = UPK(s[tt][1]);
                    e[tt] = va.x * tanh_f(x0.x) + va.y * tanh_f(x0.y) +
                            vb.x * tanh_f(x1.x) + vb.y * tanh_f(x1.y);
                }
#pragma unroll
                for (int off = 16; off; off >>= 1) {
#pragma unroll
                    for (int tt = 0; tt < 8; tt++)
                        e[tt] += __shfl_xor_sync(0xffffffffu, e[tt], off);
                }
                if (lane == 0) {
                    const unsigned char* mb = mask + (size_t)b * T_LEN + tbb;
#pragma unroll
                    for (int tt = 0; tt < 8; tt++) {
                        // |e| <= ||v||_1 ~ 15 -> exp fp32-safe without max-sub
                        float ex = mb[tt] ? 0.f : __expf(e[tt]);
                        e_sm[tbb + tt] = ex;
                        S_loc += ex;
                    }
                }
            }
            __syncwarp();
            if (lane == 0) mbar_arrive(mbar0 + c * 8);  // publish chunk c
        }
        if (lane == 0) red[w] = S_loc;
    } else {
        // ================== CONTEXT CONSUMER WARPS ==================
        const int cw = w - 8;
        const float4* mem4 = (const float4*)(memory + (size_t)b * T_LEN * EMB);
        unsigned long long acc[4][2];
#pragma unroll
        for (int j = 0; j < 4; j++) acc[j][0] = acc[j][1] = 0ull;

        for (int c = 0; c < 8; c++) {
            mbar_wait(mbar0 + c * 8, 0);  // wait chunk c energies (acquire)
            const int tb = c * 128 + cw * 16;
#pragma unroll 2
            for (int tt = 0; tt < 16; tt += 2) {
                float4 m0[4], m1[4];
#pragma unroll
                for (int j = 0; j < 4; j++)
                    m0[j] = __ldcs(&mem4[(size_t)(tb + tt) * 128 + lane + 32 * j]);
#pragma unroll
                for (int j = 0; j < 4; j++)
                    m1[j] =
                        __ldcs(&mem4[(size_t)(tb + tt + 1) * 128 + lane + 32 * j]);
                float w0 = e_sm[tb + tt], w1 = e_sm[tb + tt + 1];
                unsigned long long W0 = PK(w0, w0), W1 = PK(w1, w1);
#pragma unroll
                for (int j = 0; j < 4; j++) {
                    acc[j][0] = FMA2(W0, PK(m0[j].x, m0[j].y), acc[j][0]);
                    acc[j][1] = FMA2(W0, PK(m0[j].z, m0[j].w), acc[j][1]);
                }
#pragma unroll
                for (int j = 0; j < 4; j++) {
                    acc[j][0] = FMA2(W1, PK(m1[j].x, m1[j].y), acc[j][0]);
                    acc[j][1] = FMA2(W1, PK(m1[j].z, m1[j].w), acc[j][1]);
                }
            }
        }
        // park per-warp partials (raw, unnormalized)
#pragma unroll
        for (int j = 0; j < 4; j++) {
            float2 x0 = UPK(acc[j][0]), x1 = UPK(acc[j][1]);
            scr[cw * 128 + lane + 32 * j] = make_float4(x0.x, x0.y, x1.x, x1.y);
        }
    }

    __syncthreads();  // all: S partials + scr + e_sm final

    float S = red[0] + red[1] + red[2] + red[3] + red[4] + red[5] + red[6] + red[7];
    const float invS = 1.0f / S;

    float* oW = outW + (size_t)b * T_LEN;
    for (int i = tid; i < T_LEN; i += 512) oW[i] = e_sm[i] * invS;

    if (tid < 128) {
        float4 o = make_float4(0.f, 0.f, 0.f, 0.f);
#pragma unroll
        for (int q = 0; q < 8; q++) {
            float4 sq = scr[q * 128 + tid];
            o.x += sq.x; o.y += sq.y; o.z += sq.z; o.w += sq.w;
        }
        o.x *= invS; o.y *= invS; o.z *= invS; o.w *= invS;
        ((float4*)outC)[(size_t)b * 128 + tid] = o;
    }
}

extern "C" void kernel_launch(void* const* d_in, const int* in_sizes, int n_in,
                              void* d_out, int out_size) {
    const float* query = (const float*)d_in[0];
    const float* memory = (const float*)d_in[1];
    const float* pmem = (const float*)d_in[2];
    const float* awcat = (const float*)d_in[3];
    const unsigned char* mask = (const unsigned char*)d_in[4];
    const float* wq = (const float*)d_in[5];
    const float* wconv = (const float*)d_in[6];
    const float* wll = (const float*)d_in[7];
    const float* v = (const float*)d_in[8];

    float* outC = (float*)d_out;               // (B, 512)
    float* outW = outC + (size_t)B_LEN * EMB;  // (B, T)

    cudaFuncSetAttribute(attn_fused, cudaFuncAttributeMaxDynamicSharedMemorySize,
                         SMEM_BYTES);
    attn_fused<<<B_LEN, 512, SMEM_BYTES>>>(query, memory, pmem, awcat, mask, wq,
                                           wconv, wll, v, outC, outW);
}